// round 10
// baseline (speedup 1.0000x reference)
#include <cuda_runtime.h>
#include <cuda_fp16.h>
#include <cstdint>
#include <cstddef>

#define DI __device__ __forceinline__

// ---------------------------------------------------------------------------
// Problem / tile geometry
// ---------------------------------------------------------------------------
namespace cfg {
constexpr int Bn = 16384, En = 1024, Hn = 1024;
constexpr int TM = 128;            // rows per CTA
constexpr int TJ = 32;             // j-columns per gate per CTA
constexpr int KC = 64;             // K elements per pipeline stage
constexpr int ITERS = 32;          // 16 chunks x@Wi + 16 chunks h@Ws
constexpr int STAGES = 3;
constexpr int NA = 6 * TJ;         // 192 gemm cols phase A
constexpr int NB = 5 * TJ;         // 160 phase B (gate 5 = x@Wi only)

constexpr int A_BYTES = TM * KC * 2;            // 16384
constexpr int B_BYTES = NA * KC * 2;            // 24576
constexpr int STAGE_BYTES = A_BYTES + B_BYTES;  // 40960
constexpr int STG_OFF = 1024;
constexpr int SMEM_TOTAL = STG_OFF + STAGES * STAGE_BYTES;  // 123904
}  // namespace cfg

// fp16 scratch (static device arrays -> no runtime allocation)
__device__ __half g_xh[(size_t)cfg::Bn * cfg::En];
__device__ __half g_hh[(size_t)cfg::Bn * cfg::Hn];
__device__ __half g_wih[(size_t)6 * cfg::Hn * cfg::En];
__device__ __half g_wsh[(size_t)5 * cfg::Hn * cfg::Hn];

// ---------------------------------------------------------------------------
// PTX helpers (baseline ISA only: cp.async, ldmatrix, mma.sync)
// ---------------------------------------------------------------------------
DI uint32_t smem_u32(const void* p) {
    uint32_t a;
    asm("{ .reg .u64 t; cvta.to.shared.u64 t, %1; cvt.u32.u64 %0, t; }"
        : "=r"(a) : "l"(p));
    return a;
}

DI uint32_t swz(uint32_t o) { return o ^ ((o >> 3) & 0x70u); }

DI void cp16(uint32_t dst, const void* src) {
    asm volatile("cp.async.cg.shared.global [%0], [%1], 16;"
                 :: "r"(dst), "l"(__cvta_generic_to_global(src)) : "memory");
}
DI void cp_commit() { asm volatile("cp.async.commit_group;" ::: "memory"); }
template <int N>
DI void cp_wait() {
    asm volatile("cp.async.wait_group %0;" :: "n"(N) : "memory");
}

DI void ldsm_x4(uint32_t* r, uint32_t addr) {
    asm volatile("ldmatrix.sync.aligned.m8n8.x4.shared.b16 {%0,%1,%2,%3}, [%4];"
                 : "=r"(r[0]), "=r"(r[1]), "=r"(r[2]), "=r"(r[3]) : "r"(addr));
}
DI void ldsm_x2(uint32_t& b0, uint32_t& b1, uint32_t addr) {
    asm volatile("ldmatrix.sync.aligned.m8n8.x2.shared.b16 {%0,%1}, [%2];"
                 : "=r"(b0), "=r"(b1) : "r"(addr));
}

DI void mma16816(float* c, const uint32_t* a, uint32_t b0, uint32_t b1) {
    asm volatile(
        "mma.sync.aligned.m16n8k16.row.col.f32.f16.f16.f32 "
        "{%0,%1,%2,%3}, {%4,%5,%6,%7}, {%8,%9}, {%0,%1,%2,%3};"
        : "+f"(c[0]), "+f"(c[1]), "+f"(c[2]), "+f"(c[3])
        : "r"(a[0]), "r"(a[1]), "r"(a[2]), "r"(a[3]), "r"(b0), "r"(b1));
}

DI float sigm(float x) { return 1.0f / (1.0f + __expf(-x)); }
DI float tanh_(float x) { return 1.0f - 2.0f / (1.0f + __expf(2.0f * x)); }

// ---------------------------------------------------------------------------
// fp32 -> fp16 conversion
// ---------------------------------------------------------------------------
__global__ __launch_bounds__(256) void cvt_kernel(const float4* __restrict__ src,
                                                  __half2* __restrict__ dst,
                                                  int n4) {
    int i = blockIdx.x * blockDim.x + threadIdx.x;
    int stride = gridDim.x * blockDim.x;
    for (; i < n4; i += stride) {
        float4 v = src[i];
        dst[2 * i]     = __floats2half2_rn(v.x, v.y);
        dst[2 * i + 1] = __floats2half2_rn(v.z, v.w);
    }
}

// ---------------------------------------------------------------------------
// Chunk loader: A tile (128x64) + B tile (192/160 x 64), SW128 swizzle
// ---------------------------------------------------------------------------
DI void load_chunk(int it, uint32_t stage_base, int m0, int j0, int tid) {
    using namespace cfg;
    const int kc = (it < 16) ? it : it - 16;
    const bool pa = (it < 16);
    const __half* Asrc = pa ? g_xh : g_hh;
    const __half* Bsrc = pa ? g_wih : g_wsh;

    // A: 128 rows x 64 halves (128B rows)
    for (int idx = tid; idx < 1024; idx += 256) {
        int rr = idx >> 3, q = idx & 7;
        const __half* p = Asrc + (size_t)(m0 + rr) * 1024 + kc * 64 + q * 8;
        cp16(stage_base + swz((uint32_t)(rr * 128 + q * 16)), p);
    }
    // B: gate-stacked weight rows; smem row n = g*32 + jj
    const uint32_t bbase = stage_base + A_BYTES;
    const int nOps = pa ? (192 * 8) : (160 * 8);
    for (int idx = tid; idx < nOps; idx += 256) {
        int n = idx >> 3, q = idx & 7;
        int g = n >> 5, jj = n & 31;
        const __half* p =
            Bsrc + (size_t)(g * 1024 + j0 + jj) * 1024 + kc * 64 + q * 8;
        cp16(bbase + swz((uint32_t)(n * 128 + q * 16)), p);
    }
}

// ---------------------------------------------------------------------------
// Per-chunk compute: warp tile 32x96, NT n-tiles (12 phase A; 8 for warp_n=1
// in phase B, since gate-5 cols aren't loaded then)
// ---------------------------------------------------------------------------
template <int NT>
DI void compute_chunk(uint32_t abase, uint32_t bbase, int lane,
                      int warp_m, int warp_n, float (&acc)[2][12][4]) {
    const uint32_t a_row = (uint32_t)(warp_m * 32 + (lane & 15)) * 128u;
    const uint32_t a_kb  = ((uint32_t)(lane >> 4) & 1u) * 16u;
    const int l15 = lane & 15;
    const uint32_t b_row = (uint32_t)(warp_n * 96 + (l15 & 7)) * 128u;
    const uint32_t b_kb  = (uint32_t)(l15 >> 3) * 16u;
#pragma unroll
    for (int ks = 0; ks < 4; ++ks) {
        uint32_t a[2][4];
#pragma unroll
        for (int mt = 0; mt < 2; ++mt)
            ldsm_x4(a[mt], abase + swz(a_row + mt * 2048u + a_kb + ks * 32u));
#pragma unroll
        for (int nt = 0; nt < NT; ++nt) {
            uint32_t b0, b1;
            ldsm_x2(b0, b1, bbase + swz(b_row + nt * 1024u + b_kb + ks * 32u));
            mma16816(acc[0][nt], a[0], b0, b1);
            mma16816(acc[1][nt], a[1], b0, b1);
        }
    }
}

// ---------------------------------------------------------------------------
// Main fused LSTM kernel
// ---------------------------------------------------------------------------
__global__ __launch_bounds__(256, 1)
void lstm_main(const float* __restrict__ c_in,
               const float* __restrict__ bi,
               const float* __restrict__ bs,
               float* __restrict__ out,
               float* __restrict__ mem) {
    using namespace cfg;
    extern __shared__ char smem[];
    const uint32_t sbase = smem_u32(smem);
    const int tid = threadIdx.x;
    const int lane = tid & 31;
    const int wid = tid >> 5;
    const int warp_m = wid & 3;     // 4 row groups of 32
    const int warp_n = wid >> 2;    // 2 col groups of 96
    const int mb = blockIdx.x & 127;
    const int jb = blockIdx.x >> 7;
    const int m0 = mb * TM;
    const int j0 = jb * TJ;

    float* sb = reinterpret_cast<float*>(smem);  // 192 fused biases

    // fused bias into SMEM (gate 5 has no bs)
    if (tid < 192) {
        int g = tid >> 5, jj = tid & 31;
        float b = bi[g * 1024 + j0 + jj];
        if (g < 5) b += bs[g * 1024 + j0 + jj];
        sb[tid] = b;
    }

    // ---- prologue: fill 3 stages ----
    for (int it = 0; it < STAGES; ++it) {
        load_chunk(it, sbase + STG_OFF + it * STAGE_BYTES, m0, j0, tid);
        cp_commit();
    }

    float acc[2][12][4];
#pragma unroll
    for (int mt = 0; mt < 2; ++mt)
#pragma unroll
        for (int nt = 0; nt < 12; ++nt)
#pragma unroll
            for (int q = 0; q < 4; ++q) acc[mt][nt][q] = 0.0f;

    // ---- pipelined mainloop ----
    for (int it = 0; it < ITERS; ++it) {
        const int s = it % 3;
        if (it < ITERS - 2) cp_wait<2>(); else cp_wait<0>();
        __syncthreads();

        const uint32_t abase = sbase + STG_OFF + s * STAGE_BYTES;
        const uint32_t bbase = abase + A_BYTES;
        if (it < 16 || warp_n == 0)
            compute_chunk<12>(abase, bbase, lane, warp_m, warp_n, acc);
        else
            compute_chunk<8>(abase, bbase, lane, warp_m, warp_n, acc);

        if (it + STAGES < ITERS) {
            __syncthreads();   // all warps done reading stage s
            load_chunk(it + STAGES, sbase + STG_OFF + s * STAGE_BYTES, m0, j0, tid);
            cp_commit();
        }
    }
    __syncthreads();

    // ---- epilogue: exchange accum via SMEM so each thread sees all 6 gates --
    float* sacc = reinterpret_cast<float*>(smem + STG_OFF);  // [128][200]
#pragma unroll
    for (int mt = 0; mt < 2; ++mt) {
#pragma unroll
        for (int nt = 0; nt < 12; ++nt) {
            int r = warp_m * 32 + mt * 16 + (lane >> 2);
            int c = warp_n * 96 + nt * 8 + 2 * (lane & 3);
            *reinterpret_cast<float2*>(&sacc[r * 200 + c]) =
                make_float2(acc[mt][nt][0], acc[mt][nt][1]);
            *reinterpret_cast<float2*>(&sacc[(r + 8) * 200 + c]) =
                make_float2(acc[mt][nt][2], acc[mt][nt][3]);
        }
    }
    __syncthreads();

    // gate math + direct coalesced writeback (32 floats per row per warp)
#pragma unroll
    for (int e = 0; e < 16; ++e) {
        int idx = e * 256 + tid;       // 0..4095
        int r = idx >> 5, jj = idx & 31;
        const float* row = &sacc[r * 200];
        float gi = sigm(row[jj]        + sb[jj]);
        float gf = sigm(row[32 + jj]   + sb[32 + jj]);
        float gm = tanh_(row[64 + jj]  + sb[64 + jj]);
        float go = sigm(row[96 + jj]   + sb[96 + jj]);
        float gh = sigm(row[128 + jj]  + sb[128 + jj]);
        float hp =      row[160 + jj]  + sb[160 + jj];
        size_t g = (size_t)(m0 + r) * 1024 + j0 + jj;
        float cv = c_in[g];
        float me = gi * gm + gf * cv;
        float o0 = go * tanh_(me);
        out[g] = gh * o0 + (1.0f - gh) * hp;
        mem[g] = me;
    }
}

// ---------------------------------------------------------------------------
// Launch
// ---------------------------------------------------------------------------
extern "C" void kernel_launch(void* const* d_in, const int* in_sizes, int n_in,
                              void* d_out, int out_size) {
    using namespace cfg;
    (void)in_sizes; (void)n_in; (void)out_size;
    const float* x  = (const float*)d_in[0];
    const float* h  = (const float*)d_in[1];
    const float* c  = (const float*)d_in[2];
    const float* Wi = (const float*)d_in[3];
    const float* bi = (const float*)d_in[4];
    const float* Ws = (const float*)d_in[5];
    const float* bs = (const float*)d_in[6];
    float* out = (float*)d_out;
    float* mem = out + (size_t)Bn * Hn;

    void *xh, *hh, *wih, *wsh;
    cudaGetSymbolAddress(&xh, g_xh);
    cudaGetSymbolAddress(&hh, g_hh);
    cudaGetSymbolAddress(&wih, g_wih);
    cudaGetSymbolAddress(&wsh, g_wsh);

    cvt_kernel<<<2048, 256>>>((const float4*)x, (__half2*)xh,
                              (int)((size_t)Bn * En / 4));
    cvt_kernel<<<2048, 256>>>((const float4*)h, (__half2*)hh,
                              (int)((size_t)Bn * Hn / 4));
    cvt_kernel<<<1024, 256>>>((const float4*)Wi, (__half2*)wih,
                              (int)((size_t)6 * Hn * En / 4));
    cvt_kernel<<<1024, 256>>>((const float4*)Ws, (__half2*)wsh,
                              (int)((size_t)5 * Hn * Hn / 4));

    cudaFuncSetAttribute(lstm_main, cudaFuncAttributeMaxDynamicSharedMemorySize,
                         SMEM_TOTAL);
    lstm_main<<<(Bn / TM) * (Hn / TJ), 256, SMEM_TOTAL>>>(c, bi, bs, out, mem);
}